// round 2
// baseline (speedup 1.0000x reference)
#include <cuda_runtime.h>
#include <cuda_bf16.h>
#include <math.h>

#define NN 50000
#define EE 1600000
#define ET (EE + NN)
#define HID 128
#define FIN 39

// ---------------- scratch (device globals; no allocation allowed) ----------------
__device__ float g_h[NN * HID];
__device__ float g_tmp[NN * HID];
__device__ float g_xp[NN * HID];
__device__ float g_es[NN * 4];
__device__ float g_ed[NN * 4];
__device__ float g_hidA[NN * 64];
__device__ float g_hidB[NN * 64];
__device__ int g_deg[NN];
__device__ int g_rowstart[NN + 1];
__device__ int g_cursor[NN];
__device__ int g_csrc[ET];

// ---------------- CSR build ----------------
__global__ void zero_deg_k() {
    int i = blockIdx.x * blockDim.x + threadIdx.x;
    if (i < NN) g_deg[i] = 0;
}

__global__ void count_k(const int* __restrict__ ei) {
    int idx = blockIdx.x * blockDim.x + threadIdx.x;
    if (idx >= ET) return;
    int d = (idx < EE) ? ei[EE + idx] : (idx - EE);
    atomicAdd(&g_deg[d], 1);
}

__global__ void __launch_bounds__(1024) scan_k() {
    __shared__ int sums[1024];
    int t = threadIdx.x;
    const int CH = (NN + 1023) / 1024;  // 49
    int lo = t * CH;
    int hi = min(lo + CH, NN);
    int s = 0;
    for (int i = lo; i < hi; i++) s += g_deg[i];
    sums[t] = s;
    __syncthreads();
    // Hillis-Steele inclusive scan
    for (int off = 1; off < 1024; off <<= 1) {
        int v = (t >= off) ? sums[t - off] : 0;
        __syncthreads();
        sums[t] += v;
        __syncthreads();
    }
    int base = (t == 0) ? 0 : sums[t - 1];
    for (int i = lo; i < hi; i++) {
        g_rowstart[i] = base;
        g_cursor[i] = base;
        base += g_deg[i];
    }
    if (t == 1023) g_rowstart[NN] = sums[1023];
}

__global__ void scatter_k(const int* __restrict__ ei) {
    int idx = blockIdx.x * blockDim.x + threadIdx.x;
    if (idx >= ET) return;
    int s, d;
    if (idx < EE) { s = ei[idx]; d = ei[EE + idx]; }
    else { s = d = idx - EE; }
    int p = atomicAdd(&g_cursor[d], 1);
    g_csrc[p] = s;
}

// ---------------- encoder layer 1 (K=39) ----------------
__global__ void __launch_bounds__(128) enc1_k(const float* __restrict__ x,
                                              const float* __restrict__ W,
                                              const float* __restrict__ b,
                                              float* __restrict__ out) {
    __shared__ float Ws[FIN * 128];
    __shared__ float xs[4 * FIN];
    int t = threadIdx.x;
    for (int i = t; i < FIN * 128; i += 128) Ws[i] = W[i];
    float bb = b[t];
    for (int r0 = blockIdx.x * 4; r0 < NN; r0 += gridDim.x * 4) {
        __syncthreads();
        for (int i = t; i < 4 * FIN; i += 128) {
            int rr = i / FIN, k = i % FIN;
            int row = r0 + rr;
            xs[i] = (row < NN) ? x[row * FIN + k] : 0.f;
        }
        __syncthreads();
        float a0 = 0.f, a1 = 0.f, a2 = 0.f, a3 = 0.f;
#pragma unroll
        for (int k = 0; k < FIN; k++) {
            float w = Ws[k * 128 + t];
            a0 = fmaf(xs[k], w, a0);
            a1 = fmaf(xs[FIN + k], w, a1);
            a2 = fmaf(xs[2 * FIN + k], w, a2);
            a3 = fmaf(xs[3 * FIN + k], w, a3);
        }
        float acc[4] = {a0, a1, a2, a3};
#pragma unroll
        for (int rr = 0; rr < 4; rr++) {
            int row = r0 + rr;
            if (row < NN) out[row * 128 + t] = fmaxf(acc[rr] + bb, 0.f);
        }
    }
}

// ---------------- tiled GEMM: A[nrows x 128] @ B[128 x ncols] (+bias)(+relu) ----------------
#define TM 128
#define TN 64
__global__ void __launch_bounds__(256) gemm_k(const float* __restrict__ A,
                                              const float* __restrict__ B,
                                              const float* __restrict__ bias,
                                              float* __restrict__ C,
                                              int nrows, int ncols, int relu) {
    extern __shared__ float smem[];
    float* As = smem;                  // TM*128
    float* Bs = smem + TM * 128;       // 128*TN
    int rb = blockIdx.x * TM;
    int cb = blockIdx.y * TN;
    int tid = threadIdx.x;

    // load B tile (128 x 64)
    for (int i = tid; i < 128 * 16; i += 256) {
        int k = i >> 4, j4 = i & 15;
        float4 v = *(const float4*)(B + k * ncols + cb + j4 * 4);
        *(float4*)(Bs + k * TN + j4 * 4) = v;
    }
    // load A tile (128 x 128)
    for (int i = tid; i < TM * 32; i += 256) {
        int r = i >> 5, k4 = i & 31;
        int row = rb + r;
        float4 v = make_float4(0.f, 0.f, 0.f, 0.f);
        if (row < nrows) v = *(const float4*)(A + row * 128 + k4 * 4);
        *(float4*)(As + r * 128 + k4 * 4) = v;
    }
    __syncthreads();

    int tx = tid & 15, ty = tid >> 4;
    const float* Ap = As + ty * 8 * 128;
    const float* Bp = Bs + tx * 4;
    float acc[8][4];
#pragma unroll
    for (int r = 0; r < 8; r++)
#pragma unroll
        for (int c = 0; c < 4; c++) acc[r][c] = 0.f;

#pragma unroll 8
    for (int k = 0; k < 128; k++) {
        float4 bv = *(const float4*)(Bp + k * TN);
#pragma unroll
        for (int r = 0; r < 8; r++) {
            float a = Ap[r * 128 + k];
            acc[r][0] = fmaf(a, bv.x, acc[r][0]);
            acc[r][1] = fmaf(a, bv.y, acc[r][1]);
            acc[r][2] = fmaf(a, bv.z, acc[r][2]);
            acc[r][3] = fmaf(a, bv.w, acc[r][3]);
        }
    }

    int col = cb + tx * 4;
    float4 bvv = make_float4(0.f, 0.f, 0.f, 0.f);
    if (bias) bvv = *(const float4*)(bias + col);
#pragma unroll
    for (int r = 0; r < 8; r++) {
        int row = rb + ty * 8 + r;
        if (row < nrows) {
            float4 o;
            o.x = acc[r][0] + bvv.x;
            o.y = acc[r][1] + bvv.y;
            o.z = acc[r][2] + bvv.z;
            o.w = acc[r][3] + bvv.w;
            if (relu) {
                o.x = fmaxf(o.x, 0.f); o.y = fmaxf(o.y, 0.f);
                o.z = fmaxf(o.z, 0.f); o.w = fmaxf(o.w, 0.f);
            }
            *(float4*)(C + row * ncols + col) = o;
        }
    }
}

// ---------------- es/ed: per-node attention logits ----------------
__global__ void __launch_bounds__(256) esed_k(const float* __restrict__ xp,
                                              const float* __restrict__ a_s,
                                              const float* __restrict__ a_d) {
    int n = (blockIdx.x * 256 + threadIdx.x) >> 5;
    if (n >= NN) return;
    int lane = threadIdx.x & 31;
    float4 v = *(const float4*)(xp + n * 128 + lane * 4);
    float4 s4 = *(const float4*)(a_s + lane * 4);
    float4 d4 = *(const float4*)(a_d + lane * 4);
    float ps = v.x * s4.x + v.y * s4.y + v.z * s4.z + v.w * s4.w;
    float pd = v.x * d4.x + v.y * d4.y + v.z * d4.z + v.w * d4.w;
#pragma unroll
    for (int off = 4; off >= 1; off >>= 1) {
        ps += __shfl_xor_sync(0xffffffffu, ps, off);
        pd += __shfl_xor_sync(0xffffffffu, pd, off);
    }
    if ((lane & 7) == 0) {
        g_es[n * 4 + (lane >> 3)] = ps;
        g_ed[n * 4 + (lane >> 3)] = pd;
    }
}

// ---------------- gather: softmax-aggregate + bias + residual + LN + relu, warp per dst ----------------
__global__ void __launch_bounds__(256) gather_k(const float* __restrict__ xp,
                                                float* __restrict__ h,
                                                const float* __restrict__ bc,
                                                const float* __restrict__ gam,
                                                const float* __restrict__ bet) {
    int d = (blockIdx.x * 256 + threadIdx.x) >> 5;
    if (d >= NN) return;
    int lane = threadIdx.x & 31;
    int hh = lane >> 3;
    float edc = g_ed[d * 4 + hh];
    int beg = g_rowstart[d], end = g_rowstart[d + 1];

    // pass 1: exact per-head max
    float m = -3.4e38f;
    for (int i = beg; i < end; i++) {
        int s = g_csrc[i];
        float e = g_es[s * 4 + hh] + edc;
        e = (e > 0.f) ? e : 0.2f * e;
        m = fmaxf(m, e);
    }
    // pass 2: exp-sum + weighted accumulate
    float ssum = 0.f;
    float4 acc = make_float4(0.f, 0.f, 0.f, 0.f);
    for (int i = beg; i < end; i++) {
        int s = g_csrc[i];
        float e = g_es[s * 4 + hh] + edc;
        e = (e > 0.f) ? e : 0.2f * e;
        float w = __expf(e - m);
        float4 v = *(const float4*)(xp + s * 128 + lane * 4);
        ssum += w;
        acc.x = fmaf(w, v.x, acc.x);
        acc.y = fmaf(w, v.y, acc.y);
        acc.z = fmaf(w, v.z, acc.z);
        acc.w = fmaf(w, v.w, acc.w);
    }
    float inv = 1.f / ssum;

    float4 hv = *(const float4*)(h + d * 128 + lane * 4);
    float4 bcv = *(const float4*)(bc + lane * 4);
    float4 y;
    y.x = acc.x * inv + bcv.x + hv.x;
    y.y = acc.y * inv + bcv.y + hv.y;
    y.z = acc.z * inv + bcv.z + hv.z;
    y.w = acc.w * inv + bcv.w + hv.w;

    // LayerNorm over 128 (full warp reduce)
    float s1 = y.x + y.y + y.z + y.w;
#pragma unroll
    for (int off = 16; off >= 1; off >>= 1) s1 += __shfl_xor_sync(0xffffffffu, s1, off);
    float mean = s1 * (1.f / 128.f);
    float dx = y.x - mean, dy = y.y - mean, dz = y.z - mean, dw = y.w - mean;
    float sq = dx * dx + dy * dy + dz * dz + dw * dw;
#pragma unroll
    for (int off = 16; off >= 1; off >>= 1) sq += __shfl_xor_sync(0xffffffffu, sq, off);
    float rstd = rsqrtf(sq * (1.f / 128.f) + 1e-5f);

    float4 g4 = *(const float4*)(gam + lane * 4);
    float4 b4 = *(const float4*)(bet + lane * 4);
    float4 o;
    o.x = fmaxf(dx * rstd * g4.x + b4.x, 0.f);
    o.y = fmaxf(dy * rstd * g4.y + b4.y, 0.f);
    o.z = fmaxf(dz * rstd * g4.z + b4.z, 0.f);
    o.w = fmaxf(dw * rstd * g4.w + b4.w, 0.f);
    *(float4*)(h + d * 128 + lane * 4) = o;
}

// ---------------- output heads ----------------
__device__ __forceinline__ float softplusf(float x) {
    if (x > 20.f) return x;
    return log1pf(__expf(x));
}

__global__ void __launch_bounds__(256) heads_k(const float* __restrict__ w2i,
                                               const float* __restrict__ b2i,
                                               const float* __restrict__ w2t,
                                               const float* __restrict__ b2t,
                                               float* __restrict__ out) {
    __shared__ float wi[64 * 3];
    __shared__ float wt[64 * 2];
    int t = threadIdx.x;
    if (t < 192) wi[t] = w2i[t];
    if (t < 128) wt[t] = w2t[t];
    __syncthreads();
    int n = blockIdx.x * 256 + t;
    if (n >= NN) return;
    float a0 = 0.f, a1 = 0.f, a2 = 0.f;
#pragma unroll 8
    for (int k = 0; k < 64; k++) {
        float v = g_hidA[n * 64 + k];
        a0 = fmaf(v, wi[k * 3 + 0], a0);
        a1 = fmaf(v, wi[k * 3 + 1], a1);
        a2 = fmaf(v, wi[k * 3 + 2], a2);
    }
    out[n * 3 + 0] = a0 + b2i[0];
    out[n * 3 + 1] = a1 + b2i[1];
    out[n * 3 + 2] = a2 + b2i[2];
    float t0 = 0.f, t1 = 0.f;
#pragma unroll 8
    for (int k = 0; k < 64; k++) {
        float v = g_hidB[n * 64 + k];
        t0 = fmaf(v, wt[k * 2 + 0], t0);
        t1 = fmaf(v, wt[k * 2 + 1], t1);
    }
    out[3 * NN + n * 2 + 0] = softplusf(t0 + b2t[0]);
    out[3 * NN + n * 2 + 1] = softplusf(t1 + b2t[1]);
}

// ---------------- launch ----------------
extern "C" void kernel_launch(void* const* d_in, const int* in_sizes, int n_in,
                              void* d_out, int out_size) {
    const float* x      = (const float*)d_in[0];
    const int*   ei     = (const int*)d_in[1];
    const float* enc_w1 = (const float*)d_in[2];
    const float* enc_b1 = (const float*)d_in[3];
    const float* enc_w2 = (const float*)d_in[4];
    const float* enc_b2 = (const float*)d_in[5];
    const float* W[3]  = {(const float*)d_in[6],  (const float*)d_in[12], (const float*)d_in[18]};
    const float* As[3] = {(const float*)d_in[7],  (const float*)d_in[13], (const float*)d_in[19]};
    const float* Ad[3] = {(const float*)d_in[8],  (const float*)d_in[14], (const float*)d_in[20]};
    const float* Bc[3] = {(const float*)d_in[9],  (const float*)d_in[15], (const float*)d_in[21]};
    const float* Gm[3] = {(const float*)d_in[10], (const float*)d_in[16], (const float*)d_in[22]};
    const float* Be[3] = {(const float*)d_in[11], (const float*)d_in[17], (const float*)d_in[23]};
    const float* imp_w1 = (const float*)d_in[24];
    const float* imp_b1 = (const float*)d_in[25];
    const float* imp_w2 = (const float*)d_in[26];
    const float* imp_b2 = (const float*)d_in[27];
    const float* tim_w1 = (const float*)d_in[28];
    const float* tim_b1 = (const float*)d_in[29];
    const float* tim_w2 = (const float*)d_in[30];
    const float* tim_b2 = (const float*)d_in[31];
    float* out = (float*)d_out;

    float *p_h, *p_tmp, *p_xp;
    cudaGetSymbolAddress((void**)&p_h, g_h);
    cudaGetSymbolAddress((void**)&p_tmp, g_tmp);
    cudaGetSymbolAddress((void**)&p_xp, g_xp);
    float *p_hidA, *p_hidB;
    cudaGetSymbolAddress((void**)&p_hidA, g_hidA);
    cudaGetSymbolAddress((void**)&p_hidB, g_hidB);

    cudaFuncSetAttribute(gemm_k, cudaFuncAttributeMaxDynamicSharedMemorySize, 98304);
    const int GEMM_SMEM = (TM * 128 + 128 * TN) * 4;

    // CSR build (once; reused by all 3 layers)
    zero_deg_k<<<(NN + 255) / 256, 256>>>();
    count_k<<<(ET + 255) / 256, 256>>>(ei);
    scan_k<<<1, 1024>>>();
    scatter_k<<<(ET + 255) / 256, 256>>>(ei);

    // encoder
    enc1_k<<<2048, 128>>>(x, enc_w1, enc_b1, p_tmp);
    {
        dim3 g((NN + TM - 1) / TM, 2);
        gemm_k<<<g, 256, GEMM_SMEM>>>(p_tmp, enc_w2, enc_b2, p_h, NN, 128, 0);
    }

    // 3 GAT layers
    for (int l = 0; l < 3; l++) {
        dim3 g((NN + TM - 1) / TM, 2);
        gemm_k<<<g, 256, GEMM_SMEM>>>(p_h, W[l], nullptr, p_xp, NN, 128, 0);
        esed_k<<<(NN * 32 + 255) / 256, 256>>>(p_xp, As[l], Ad[l]);
        gather_k<<<(NN * 32 + 255) / 256, 256>>>(p_xp, p_h, Bc[l], Gm[l], Be[l]);
    }

    // heads
    {
        dim3 g((NN + TM - 1) / TM, 1);
        gemm_k<<<g, 256, GEMM_SMEM>>>(p_h, imp_w1, imp_b1, p_hidA, NN, 64, 1);
        gemm_k<<<g, 256, GEMM_SMEM>>>(p_h, tim_w1, tim_b1, p_hidB, NN, 64, 1);
    }
    heads_k<<<(NN + 255) / 256, 256>>>(imp_w2, imp_b2, tim_w2, tim_b2, out);
}

// round 5
// speedup vs baseline: 1.1448x; 1.1448x over previous
#include <cuda_runtime.h>
#include <cuda_bf16.h>
#include <math.h>
#include <stdint.h>

#define NN 50000
#define EE 1600000
#define ET (EE + NN)
#define HID 128
#define FIN 39

// ---------------- scratch (device globals; no allocation allowed) ----------------
__device__ float g_h[NN * HID];
__device__ float g_tmp[NN * HID];
__device__ float g_xp[NN * HID];
__device__ float g_es[NN * 4];
__device__ float g_ed[NN * 4];
__device__ float g_hidA[NN * 64];
__device__ float g_hidB[NN * 64];
__device__ int g_deg[NN];
__device__ int g_rowstart[NN + 1];
__device__ int g_cursor[NN];
__device__ int g_csrc[ET];
// pre-split weight images, linear [N][K] bf16 (6 matrices x 128x128 max)
__device__ __nv_bfloat16 g_wHi[6 * 128 * 128];
__device__ __nv_bfloat16 g_wLo[6 * 128 * 128];

// ---------------- CSR build ----------------
__global__ void count_k(const int* __restrict__ ei) {
    int idx = blockIdx.x * blockDim.x + threadIdx.x;
    if (idx >= ET) return;
    int d = (idx < EE) ? ei[EE + idx] : (idx - EE);
    atomicAdd(&g_deg[d], 1);
}

__global__ void __launch_bounds__(1024) scan_k() {
    __shared__ int sums[1024];
    int t = threadIdx.x;
    const int CH = (NN + 1023) / 1024;
    int lo = t * CH;
    int hi = min(lo + CH, NN);
    int s = 0;
    for (int i = lo; i < hi; i++) s += g_deg[i];
    sums[t] = s;
    __syncthreads();
    for (int off = 1; off < 1024; off <<= 1) {
        int v = (t >= off) ? sums[t - off] : 0;
        __syncthreads();
        sums[t] += v;
        __syncthreads();
    }
    int base = (t == 0) ? 0 : sums[t - 1];
    for (int i = lo; i < hi; i++) {
        g_rowstart[i] = base;
        g_cursor[i] = base;
        base += g_deg[i];
    }
    if (t == 1023) g_rowstart[NN] = sums[1023];
}

__global__ void scatter_k(const int* __restrict__ ei) {
    int idx = blockIdx.x * blockDim.x + threadIdx.x;
    if (idx >= ET) return;
    int s, d;
    if (idx < EE) { s = ei[idx]; d = ei[EE + idx]; }
    else { s = d = idx - EE; }
    int p = atomicAdd(&g_cursor[d], 1);
    g_csrc[p] = s;
}

// ---------------- weight prep: transpose + bf16 hi/lo split, linear [N][K] ----------------
__global__ void __launch_bounds__(256) prep_w_k(const float* __restrict__ w0,
                                                const float* __restrict__ w1,
                                                const float* __restrict__ w2,
                                                const float* __restrict__ w3,
                                                const float* __restrict__ w4,
                                                const float* __restrict__ w5) {
    const float* Wm[6] = {w0, w1, w2, w3, w4, w5};
    const int ncs[6] = {128, 128, 128, 128, 64, 64};
    int m = blockIdx.x;
    const float* B = Wm[m];
    int NC = ncs[m];
    __nv_bfloat16* hi = g_wHi + m * 128 * 128;
    __nv_bfloat16* lo = g_wLo + m * 128 * 128;
    int total = NC * 128;
    for (int i = threadIdx.x; i < total; i += 256) {
        int n = i >> 7, k = i & 127;
        float b = B[k * NC + n];
        __nv_bfloat16 h = __float2bfloat16(b);
        hi[i] = h;
        lo[i] = __float2bfloat16(b - __bfloat162float(h));
    }
}

// ---------------- encoder layer 1 (K=39, FFMA) ----------------
__global__ void __launch_bounds__(128) enc1_k(const float* __restrict__ x,
                                              const float* __restrict__ W,
                                              const float* __restrict__ b,
                                              float* __restrict__ out) {
    __shared__ float Ws[FIN * 128];
    __shared__ float xs[4 * FIN];
    int t = threadIdx.x;
    for (int i = t; i < FIN * 128; i += 128) Ws[i] = W[i];
    float bb = b[t];
    for (int r0 = blockIdx.x * 4; r0 < NN; r0 += gridDim.x * 4) {
        __syncthreads();
        for (int i = t; i < 4 * FIN; i += 128) {
            int rr = i / FIN, k = i % FIN;
            int row = r0 + rr;
            xs[i] = (row < NN) ? x[row * FIN + k] : 0.f;
        }
        __syncthreads();
        float a0 = 0.f, a1 = 0.f, a2 = 0.f, a3 = 0.f;
#pragma unroll
        for (int k = 0; k < FIN; k++) {
            float w = Ws[k * 128 + t];
            a0 = fmaf(xs[k], w, a0);
            a1 = fmaf(xs[FIN + k], w, a1);
            a2 = fmaf(xs[2 * FIN + k], w, a2);
            a3 = fmaf(xs[3 * FIN + k], w, a3);
        }
        float acc[4] = {a0, a1, a2, a3};
#pragma unroll
        for (int rr = 0; rr < 4; rr++) {
            int row = r0 + rr;
            if (row < NN) out[row * 128 + t] = fmaxf(acc[rr] + bb, 0.f);
        }
    }
}

// ---------------- HMMA GEMM: C[nrows x NC] = A[nrows x 128] @ B[128 x NC] ----------------
// mma.sync m16n8k16 bf16, fp32 acc. 3-pass split: Ah*Bh + Ah*Bl + Al*Bh.
// Block = 256 thr (8 warps); block tile 128 x NC; warp w -> rows [16w,16w+16).
// smem: A hi/lo [128][128] bf16 padded to 272B rows (conflict-free frag loads),
//       B hi/lo [NC][128] bf16 same padding.
#define LDB 272  // padded row stride in bytes (136 bf16)

#define MMA16816(d, A0, A1, A2, A3, B0, B1)                                     \
    asm volatile(                                                               \
        "mma.sync.aligned.m16n8k16.row.col.f32.bf16.bf16.f32 "                  \
        "{%0,%1,%2,%3}, {%4,%5,%6,%7}, {%8,%9}, {%0,%1,%2,%3};"                 \
        : "+f"((d)[0]), "+f"((d)[1]), "+f"((d)[2]), "+f"((d)[3])                \
        : "r"(A0), "r"(A1), "r"(A2), "r"(A3), "r"(B0), "r"(B1))

template <int NC, bool HAS_BIAS, bool RELU, bool ATTN>
__global__ void __launch_bounds__(256) mma_gemm_k(const float* __restrict__ A,
                                                  const __nv_bfloat16* __restrict__ Bhi,
                                                  const __nv_bfloat16* __restrict__ Blo,
                                                  const float* __restrict__ bias,
                                                  const float* __restrict__ a_s,
                                                  const float* __restrict__ a_d,
                                                  float* __restrict__ C, int nrows) {
    extern __shared__ char smem[];
    char* sAhi = smem;                     // 128*272 = 34816
    char* sAlo = smem + 34816;             // 34816
    char* sBhi = smem + 69632;             // NC*272
    char* sBlo = sBhi + NC * LDB;

    int tid = threadIdx.x;
    int rb = blockIdx.x * 128;

    // fill A (fp32 -> bf16 hi/lo split)
    for (int i = tid; i < 128 * 32; i += 256) {
        int r = i >> 5, c4 = (i & 31) * 4;
        float4 v = make_float4(0.f, 0.f, 0.f, 0.f);
        if (rb + r < nrows) v = *(const float4*)(A + (rb + r) * 128 + c4);
        __nv_bfloat16 h0 = __float2bfloat16(v.x), h1 = __float2bfloat16(v.y);
        __nv_bfloat16 h2 = __float2bfloat16(v.z), h3 = __float2bfloat16(v.w);
        __nv_bfloat16 l0 = __float2bfloat16(v.x - __bfloat162float(h0));
        __nv_bfloat16 l1 = __float2bfloat16(v.y - __bfloat162float(h1));
        __nv_bfloat16 l2 = __float2bfloat16(v.z - __bfloat162float(h2));
        __nv_bfloat16 l3 = __float2bfloat16(v.w - __bfloat162float(h3));
        __nv_bfloat162 ph0 = __halves2bfloat162(h0, h1), ph1 = __halves2bfloat162(h2, h3);
        __nv_bfloat162 pl0 = __halves2bfloat162(l0, l1), pl1 = __halves2bfloat162(l2, l3);
        int off = r * LDB + c4 * 2;
        *(uint2*)(sAhi + off) = make_uint2(*(uint32_t*)&ph0, *(uint32_t*)&ph1);
        *(uint2*)(sAlo + off) = make_uint2(*(uint32_t*)&pl0, *(uint32_t*)&pl1);
    }
    // fill B (pre-split, linear [NC][128])
    for (int i = tid; i < NC * 16; i += 256) {
        int n = i >> 4, k8 = (i & 15) * 8;
        int off = n * LDB + k8 * 2;
        *(uint4*)(sBhi + off) = ((const uint4*)Bhi)[i];
        *(uint4*)(sBlo + off) = ((const uint4*)Blo)[i];
    }
    __syncthreads();

    int wid = tid >> 5, lane = tid & 31;
    int g = lane >> 2, t = lane & 3;
    int lrow0 = wid * 16 + g;  // local row for c0/c1; c2/c3 at +8
    constexpr int NCH = NC / 8;

    float acc[NCH][4];
#pragma unroll
    for (int n = 0; n < NCH; n++)
#pragma unroll
        for (int j = 0; j < 4; j++) acc[n][j] = 0.f;

#pragma unroll
    for (int ks = 0; ks < 8; ks++) {
        int kb = ks * 32 + t * 4;  // byte offset of k = ks*16 + t*2
        const char* pa = sAhi + lrow0 * LDB + kb;
        uint32_t ah0 = *(const uint32_t*)(pa);
        uint32_t ah1 = *(const uint32_t*)(pa + 8 * LDB);
        uint32_t ah2 = *(const uint32_t*)(pa + 16);
        uint32_t ah3 = *(const uint32_t*)(pa + 8 * LDB + 16);
        const char* pl = sAlo + lrow0 * LDB + kb;
        uint32_t al0 = *(const uint32_t*)(pl);
        uint32_t al1 = *(const uint32_t*)(pl + 8 * LDB);
        uint32_t al2 = *(const uint32_t*)(pl + 16);
        uint32_t al3 = *(const uint32_t*)(pl + 8 * LDB + 16);
#pragma unroll
        for (int n = 0; n < NCH; n++) {
            int col = n * 8 + g;
            const char* pb = sBhi + col * LDB + kb;
            uint32_t bh0 = *(const uint32_t*)(pb);
            uint32_t bh1 = *(const uint32_t*)(pb + 16);
            const char* pbl = sBlo + col * LDB + kb;
            uint32_t bl0 = *(const uint32_t*)(pbl);
            uint32_t bl1 = *(const uint32_t*)(pbl + 16);
            MMA16816(acc[n], ah0, ah1, ah2, ah3, bh0, bh1);
            MMA16816(acc[n], ah0, ah1, ah2, ah3, bl0, bl1);
            MMA16816(acc[n], al0, al1, al2, al3, bh0, bh1);
        }
    }

    int grow0 = rb + lrow0, grow1 = grow0 + 8;

    if (ATTN) {
        float es0[4], ed0[4], es1[4], ed1[4];
#pragma unroll
        for (int h = 0; h < 4; h++) { es0[h] = 0.f; ed0[h] = 0.f; es1[h] = 0.f; ed1[h] = 0.f; }
#pragma unroll
        for (int n = 0; n < NCH; n++) {
            int col = n * 8 + t * 2;
            int h = n >> 2;
            float as0 = __ldg(a_s + col), as1 = __ldg(a_s + col + 1);
            float ad0 = __ldg(a_d + col), ad1 = __ldg(a_d + col + 1);
            es0[h] += acc[n][0] * as0 + acc[n][1] * as1;
            ed0[h] += acc[n][0] * ad0 + acc[n][1] * ad1;
            es1[h] += acc[n][2] * as0 + acc[n][3] * as1;
            ed1[h] += acc[n][2] * ad0 + acc[n][3] * ad1;
        }
#pragma unroll
        for (int h = 0; h < 4; h++) {
            es0[h] += __shfl_xor_sync(0xffffffffu, es0[h], 1);
            es0[h] += __shfl_xor_sync(0xffffffffu, es0[h], 2);
            ed0[h] += __shfl_xor_sync(0xffffffffu, ed0[h], 1);
            ed0[h] += __shfl_xor_sync(0xffffffffu, ed0[h], 2);
            es1[h] += __shfl_xor_sync(0xffffffffu, es1[h], 1);
            es1[h] += __shfl_xor_sync(0xffffffffu, es1[h], 2);
            ed1[h] += __shfl_xor_sync(0xffffffffu, ed1[h], 1);
            ed1[h] += __shfl_xor_sync(0xffffffffu, ed1[h], 2);
        }
        if (t == 0) {
            if (grow0 < nrows) {
#pragma unroll
                for (int h = 0; h < 4; h++) {
                    g_es[grow0 * 4 + h] = es0[h];
                    g_ed[grow0 * 4 + h] = ed0[h];
                }
            }
            if (grow1 < nrows) {
#pragma unroll
                for (int h = 0; h < 4; h++) {
                    g_es[grow1 * 4 + h] = es1[h];
                    g_ed[grow1 * 4 + h] = ed1[h];
                }
            }
        }
    }

#pragma unroll
    for (int n = 0; n < NCH; n++) {
        int col = n * 8 + t * 2;
        float b0 = 0.f, b1 = 0.f;
        if (HAS_BIAS) { b0 = __ldg(bias + col); b1 = __ldg(bias + col + 1); }
        float o0 = acc[n][0] + b0, o1 = acc[n][1] + b1;
        float o2 = acc[n][2] + b0, o3 = acc[n][3] + b1;
        if (RELU) {
            o0 = fmaxf(o0, 0.f); o1 = fmaxf(o1, 0.f);
            o2 = fmaxf(o2, 0.f); o3 = fmaxf(o3, 0.f);
        }
        if (grow0 < nrows) *(float2*)(C + grow0 * NC + col) = make_float2(o0, o1);
        if (grow1 < nrows) *(float2*)(C + grow1 * NC + col) = make_float2(o2, o3);
    }
}

// ---------------- gather: softmax-aggregate + bias + residual + LN + relu, warp per dst ----------------
__global__ void __launch_bounds__(256) gather_k(const float* __restrict__ xp,
                                                float* __restrict__ h,
                                                const float* __restrict__ bc,
                                                const float* __restrict__ gam,
                                                const float* __restrict__ bet) {
    int d = (blockIdx.x * 256 + threadIdx.x) >> 5;
    if (d >= NN) return;
    int lane = threadIdx.x & 31;
    int hh = lane >> 3;
    float edc = g_ed[d * 4 + hh];
    int beg = g_rowstart[d], end = g_rowstart[d + 1];

    // pass 1: exact per-head max
    float m = -3.4e38f;
    for (int i = beg; i < end; i++) {
        int s = __ldg(&g_csrc[i]);
        float e = g_es[s * 4 + hh] + edc;
        e = (e > 0.f) ? e : 0.2f * e;
        m = fmaxf(m, e);
    }
    // pass 2: exp-sum + weighted accumulate
    float ssum = 0.f;
    float4 acc = make_float4(0.f, 0.f, 0.f, 0.f);
    for (int i = beg; i < end; i++) {
        int s = __ldg(&g_csrc[i]);
        float e = g_es[s * 4 + hh] + edc;
        e = (e > 0.f) ? e : 0.2f * e;
        float w = __expf(e - m);
        float4 v = *(const float4*)(xp + s * 128 + lane * 4);
        ssum += w;
        acc.x = fmaf(w, v.x, acc.x);
        acc.y = fmaf(w, v.y, acc.y);
        acc.z = fmaf(w, v.z, acc.z);
        acc.w = fmaf(w, v.w, acc.w);
    }
    float inv = 1.f / ssum;

    float4 hv = *(const float4*)(h + d * 128 + lane * 4);
    float4 bcv = *(const float4*)(bc + lane * 4);
    float4 y;
    y.x = acc.x * inv + bcv.x + hv.x;
    y.y = acc.y * inv + bcv.y + hv.y;
    y.z = acc.z * inv + bcv.z + hv.z;
    y.w = acc.w * inv + bcv.w + hv.w;

    float s1 = y.x + y.y + y.z + y.w;
#pragma unroll
    for (int off = 16; off >= 1; off >>= 1) s1 += __shfl_xor_sync(0xffffffffu, s1, off);
    float mean = s1 * (1.f / 128.f);
    float dx = y.x - mean, dy = y.y - mean, dz = y.z - mean, dw = y.w - mean;
    float sq = dx * dx + dy * dy + dz * dz + dw * dw;
#pragma unroll
    for (int off = 16; off >= 1; off >>= 1) sq += __shfl_xor_sync(0xffffffffu, sq, off);
    float rstd = rsqrtf(sq * (1.f / 128.f) + 1e-5f);

    float4 g4 = *(const float4*)(gam + lane * 4);
    float4 b4 = *(const float4*)(bet + lane * 4);
    float4 o;
    o.x = fmaxf(dx * rstd * g4.x + b4.x, 0.f);
    o.y = fmaxf(dy * rstd * g4.y + b4.y, 0.f);
    o.z = fmaxf(dz * rstd * g4.z + b4.z, 0.f);
    o.w = fmaxf(dw * rstd * g4.w + b4.w, 0.f);
    *(float4*)(h + d * 128 + lane * 4) = o;
}

// ---------------- output heads ----------------
__device__ __forceinline__ float softplusf(float x) {
    if (x > 20.f) return x;
    return log1pf(__expf(x));
}

__global__ void __launch_bounds__(256) heads_k(const float* __restrict__ w2i,
                                               const float* __restrict__ b2i,
                                               const float* __restrict__ w2t,
                                               const float* __restrict__ b2t,
                                               float* __restrict__ out) {
    __shared__ float wi[64 * 3];
    __shared__ float wt[64 * 2];
    int t = threadIdx.x;
    if (t < 192) wi[t] = w2i[t];
    if (t < 128) wt[t] = w2t[t];
    __syncthreads();
    int n = blockIdx.x * 256 + t;
    if (n >= NN) return;
    float a0 = 0.f, a1 = 0.f, a2 = 0.f;
#pragma unroll 8
    for (int k = 0; k < 64; k++) {
        float v = g_hidA[n * 64 + k];
        a0 = fmaf(v, wi[k * 3 + 0], a0);
        a1 = fmaf(v, wi[k * 3 + 1], a1);
        a2 = fmaf(v, wi[k * 3 + 2], a2);
    }
    out[n * 3 + 0] = a0 + b2i[0];
    out[n * 3 + 1] = a1 + b2i[1];
    out[n * 3 + 2] = a2 + b2i[2];
    float t0 = 0.f, t1 = 0.f;
#pragma unroll 8
    for (int k = 0; k < 64; k++) {
        float v = g_hidB[n * 64 + k];
        t0 = fmaf(v, wt[k * 2 + 0], t0);
        t1 = fmaf(v, wt[k * 2 + 1], t1);
    }
    out[3 * NN + n * 2 + 0] = softplusf(t0 + b2t[0]);
    out[3 * NN + n * 2 + 1] = softplusf(t1 + b2t[1]);
}

// ---------------- launch ----------------
extern "C" void kernel_launch(void* const* d_in, const int* in_sizes, int n_in,
                              void* d_out, int out_size) {
    const float* x      = (const float*)d_in[0];
    const int*   ei     = (const int*)d_in[1];
    const float* enc_w1 = (const float*)d_in[2];
    const float* enc_b1 = (const float*)d_in[3];
    const float* enc_w2 = (const float*)d_in[4];
    const float* enc_b2 = (const float*)d_in[5];
    const float* W[3]  = {(const float*)d_in[6],  (const float*)d_in[12], (const float*)d_in[18]};
    const float* As[3] = {(const float*)d_in[7],  (const float*)d_in[13], (const float*)d_in[19]};
    const float* Ad[3] = {(const float*)d_in[8],  (const float*)d_in[14], (const float*)d_in[20]};
    const float* Bc[3] = {(const float*)d_in[9],  (const float*)d_in[15], (const float*)d_in[21]};
    const float* Gm[3] = {(const float*)d_in[10], (const float*)d_in[16], (const float*)d_in[22]};
    const float* Be[3] = {(const float*)d_in[11], (const float*)d_in[17], (const float*)d_in[23]};
    const float* imp_w1 = (const float*)d_in[24];
    const float* imp_b1 = (const float*)d_in[25];
    const float* imp_w2 = (const float*)d_in[26];
    const float* imp_b2 = (const float*)d_in[27];
    const float* tim_w1 = (const float*)d_in[28];
    const float* tim_b1 = (const float*)d_in[29];
    const float* tim_w2 = (const float*)d_in[30];
    const float* tim_b2 = (const float*)d_in[31];
    float* out = (float*)d_out;

    float *p_h, *p_tmp, *p_xp, *p_hidA, *p_hidB;
    cudaGetSymbolAddress((void**)&p_h, g_h);
    cudaGetSymbolAddress((void**)&p_tmp, g_tmp);
    cudaGetSymbolAddress((void**)&p_xp, g_xp);
    cudaGetSymbolAddress((void**)&p_hidA, g_hidA);
    cudaGetSymbolAddress((void**)&p_hidB, g_hidB);
    int* p_deg;
    cudaGetSymbolAddress((void**)&p_deg, g_deg);
    __nv_bfloat16 *p_wHi, *p_wLo;
    cudaGetSymbolAddress((void**)&p_wHi, g_wHi);
    cudaGetSymbolAddress((void**)&p_wLo, g_wLo);

    const int SMEM_128 = 69632 + 2 * 128 * LDB;  // 139264
    const int SMEM_64  = 69632 + 2 * 64 * LDB;   // 104448
    cudaFuncSetAttribute((const void*)mma_gemm_k<128, true, false, false>,
                         cudaFuncAttributeMaxDynamicSharedMemorySize, SMEM_128);
    cudaFuncSetAttribute((const void*)mma_gemm_k<128, false, false, true>,
                         cudaFuncAttributeMaxDynamicSharedMemorySize, SMEM_128);
    cudaFuncSetAttribute((const void*)mma_gemm_k<64, true, true, false>,
                         cudaFuncAttributeMaxDynamicSharedMemorySize, SMEM_64);

    const int NB = (NN + 127) / 128;  // 391

    // weight prep + CSR build
    prep_w_k<<<6, 256>>>(enc_w2, W[0], W[1], W[2], imp_w1, tim_w1);
    cudaMemsetAsync(p_deg, 0, NN * sizeof(int));
    count_k<<<(ET + 255) / 256, 256>>>(ei);
    scan_k<<<1, 1024>>>();
    scatter_k<<<(ET + 255) / 256, 256>>>(ei);

    // encoder
    enc1_k<<<2048, 128>>>(x, enc_w1, enc_b1, p_tmp);
    mma_gemm_k<128, true, false, false><<<NB, 256, SMEM_128>>>(
        p_tmp, p_wHi, p_wLo, enc_b2, nullptr, nullptr, p_h, NN);

    // 3 GAT layers (esed fused into GEMM epilogue)
    for (int l = 0; l < 3; l++) {
        mma_gemm_k<128, false, false, true><<<NB, 256, SMEM_128>>>(
            p_h, p_wHi + (1 + l) * 16384, p_wLo + (1 + l) * 16384, nullptr,
            As[l], Ad[l], p_xp, NN);
        gather_k<<<(NN * 32 + 255) / 256, 256>>>(p_xp, p_h, Bc[l], Gm[l], Be[l]);
    }

    // heads
    mma_gemm_k<64, true, true, false><<<NB, 256, SMEM_64>>>(
        p_h, p_wHi + 4 * 16384, p_wLo + 4 * 16384, imp_b1, nullptr, nullptr, p_hidA, NN);
    mma_gemm_k<64, true, true, false><<<NB, 256, SMEM_64>>>(
        p_h, p_wHi + 5 * 16384, p_wLo + 5 * 16384, tim_b1, nullptr, nullptr, p_hidB, NN);
    heads_k<<<(NN + 255) / 256, 256>>>(imp_w2, imp_b2, tim_w2, tim_b2, out);
}